// round 10
// baseline (speedup 1.0000x reference)
#include <cuda_runtime.h>
#include <math.h>

// ---------------- global scratch (no allocations allowed) ----------------
__device__ float q_g[4 * 1024 * 8];
__device__ float k_g[4 * 1024 * 8];
__device__ float v_g[4 * 1024 * 8];
__device__ float accp_g[1024 * 4 * 2 * 8];   // [row][head][half][8]
__device__ float sump_g[1024 * 4 * 2];       // [row][head][half]

typedef unsigned long long u64;

__device__ __forceinline__ float tanh_f(float x) {
    float y; asm("tanh.approx.f32 %0, %1;" : "=f"(y) : "f"(x)); return y;
}
__device__ __forceinline__ float sigf(float x) {
    return fmaf(0.5f, tanh_f(0.5f * x), 0.5f);
}
__device__ __forceinline__ u64 pack2(float a, float b) {
    u64 r; asm("mov.b64 %0, {%1,%2};" : "=l"(r) : "f"(a), "f"(b)); return r;
}
__device__ __forceinline__ void unpack2(u64 v, float& a, float& b) {
    asm("mov.b64 {%0,%1}, %2;" : "=f"(a), "=f"(b) : "l"(v));
}
__device__ __forceinline__ u64 fma2(u64 a, u64 b, u64 c) {
    u64 d; asm("fma.rn.f32x2 %0, %1, %2, %3;" : "=l"(d) : "l"(a), "l"(b), "l"(c)); return d;
}
__device__ __forceinline__ u64 add2(u64 a, u64 b) {
    u64 d; asm("add.rn.f32x2 %0, %1, %2;" : "=l"(d) : "l"(a), "l"(b)); return d;
}

// =====================================================================
// Kernel 1: pipelined LSTM1 + LSTM2, cell-owning threads, shuffle-combined
//   k-split partials (NO gate smem traffic, NO intra-step barriers).
//   threads 0-255  : LSTM1 — thread (j 0-63, q 0-3) owns gates
//                    {j, 64+j, 128+j, 192+j}, rows [16q,16q+16), all 8 batches.
//                    2 shfl butterfly rounds combine the 4 k-quarters; lane q
//                    then computes cell j for batches 2q,2q+1.
//   threads 256-511: LSTM2 — thread (j 0-31, q 0-7) owns gates
//                    {j, 32+j, 64+j, 96+j}, rows [12q,12q+12) of concat(h1,h2).
//                    3 shfl rounds; lane q computes cell j for batch q.
//   One __syncthreads per step. 128 CTAs x 512 threads, 8 batch rows/CTA.
// =====================================================================
__global__ void __launch_bounds__(512, 1) lstm_kernel(
    const float* __restrict__ x,
    const float* __restrict__ emb_w, const float* __restrict__ emb_b,
    const float* __restrict__ w1, const float* __restrict__ u1,
    const float* __restrict__ b1i, const float* __restrict__ b1h,
    const float* __restrict__ w2, const float* __restrict__ u2,
    const float* __restrict__ b2i, const float* __restrict__ b2h,
    const float* __restrict__ attn_w, const float* __restrict__ attn_b)
{
    extern __shared__ __align__(16) float sm[];
    float* pt1s   = sm;              // [16][64][4]  4096  (bias+emb folded, per t)
    float* pe     = pt1s + 4096;    // [16][32]      512
    float* xs     = pe + 512;       // [16][8]       128
    float* hcat   = xs + 128;       // [2][96][8]   1536
    float* embw_s = hcat + 1536;    // 32
    float* embb_s = embw_s + 32;    // 32

    const int tid = threadIdx.x;
    const int b0 = blockIdx.x * 8;

    // ---- shared prologue ----
    if (tid < 512) {
        int t = tid >> 5, e = tid & 31;
        int half = e >> 1;
        float div = __expf(-(float)(2 * half) * (9.210340371976184f / 32.0f));
        float arg = (float)t * div;
        pe[tid] = (e & 1) ? cosf(arg) : sinf(arg);
    }
    if (tid < 32) { embw_s[tid] = emb_w[tid]; embb_s[tid] = emb_b[tid]; }
    if (tid < 128) { int t = tid >> 3, b = tid & 7; xs[tid] = x[(b0 + b) * 16 + t]; }
    for (int i = tid; i < 1536; i += 512) hcat[i] = 0.f;
    __syncthreads();

    // ---- per-thread setup ----
    float wreg[64];          // A: 4 gates x 16 rows; B: 4 gates x 12 rows (48 used)
    u64 wep[4];              // A: (we1,we1) per gate;  B: (bias,bias) per gate
    float c0 = 0.f, c1 = 0.f;   // cell states (A: 2 batches; B: 1 batch in c0)
    int jj, qq;

    if (tid < 256) {
        jj = tid >> 2; qq = tid & 3;
        #pragma unroll
        for (int g = 0; g < 4; g++) {
            int gate = g * 64 + jj;
            // recurrent weights: rows [16q, 16q+16)
            const float4* up = (const float4*)(u1 + gate * 64 + qq * 16);
            #pragma unroll
            for (int t4 = 0; t4 < 4; t4++) {
                float4 v = up[t4];
                wreg[g*16 + t4*4 + 0] = v.x; wreg[g*16 + t4*4 + 1] = v.y;
                wreg[g*16 + t4*4 + 2] = v.z; wreg[g*16 + t4*4 + 3] = v.w;
            }
            // embedding fold: we1[g], and pt1s for t = 4q..4q+3
            float w1r[32];
            const float4* w1p = (const float4*)(w1 + gate * 32);
            #pragma unroll
            for (int p = 0; p < 8; p++) {
                float4 v = w1p[p];
                w1r[p*4+0] = v.x; w1r[p*4+1] = v.y; w1r[p*4+2] = v.z; w1r[p*4+3] = v.w;
            }
            float we = 0.f, wb = b1i[gate] + b1h[gate];
            #pragma unroll
            for (int e = 0; e < 32; e++) {
                we = fmaf(w1r[e], embw_s[e], we);
                wb = fmaf(w1r[e], embb_s[e], wb);
            }
            wep[g] = pack2(we, we);
            #pragma unroll
            for (int tt = 0; tt < 4; tt++) {
                int t = qq * 4 + tt;
                float s = wb;
                #pragma unroll
                for (int e = 0; e < 32; e++) s = fmaf(w1r[e], pe[t * 32 + e], s);
                pt1s[t * 256 + jj * 4 + g] = s;
            }
        }
    } else {
        int t2 = tid - 256;
        jj = t2 >> 3; qq = t2 & 7;
        #pragma unroll
        for (int g = 0; g < 4; g++) {
            int gate = g * 32 + jj;
            #pragma unroll
            for (int r = 0; r < 12; r++) {
                int row = qq * 12 + r;
                wreg[g*12 + r] = (row < 64) ? w2[gate * 64 + row]
                                            : u2[gate * 32 + (row - 64)];
            }
            float bv = b2i[gate] + b2h[gate];
            wep[g] = pack2(bv, bv);
        }
    }
    __syncthreads();

    // ---- pipelined main loop: 17 iterations, ONE barrier per step ----
    for (int i = 0; i < 17; ++i) {
        int cur = i & 1;
        const float* hc = hcat + cur * 768;
        float* hn = hcat + (cur ^ 1) * 768;

        if (tid < 256) {
            if (i < 16) {
                u64 acc[16];   // [g][bp]
                if (qq == 0) {
                    // init with bias/emb fold + x term
                    const float4 ptv = *(const float4*)&pt1s[i * 256 + jj * 4];
                    u64 pt[4] = { pack2(ptv.x, ptv.x), pack2(ptv.y, ptv.y),
                                  pack2(ptv.z, ptv.z), pack2(ptv.w, ptv.w) };
                    const u64* xp = (const u64*)&xs[i * 8];
                    u64 x0 = xp[0], x1 = xp[1], x2 = xp[2], x3 = xp[3];
                    #pragma unroll
                    for (int g = 0; g < 4; g++) {
                        acc[g*4+0] = fma2(wep[g], x0, pt[g]);
                        acc[g*4+1] = fma2(wep[g], x1, pt[g]);
                        acc[g*4+2] = fma2(wep[g], x2, pt[g]);
                        acc[g*4+3] = fma2(wep[g], x3, pt[g]);
                    }
                } else {
                    #pragma unroll
                    for (int a = 0; a < 16; a++) acc[a] = 0ULL;
                }
                const float* hk = hc + qq * 128;   // rows [16q, 16q+16)
                #pragma unroll
                for (int r = 0; r < 16; r++) {
                    ulonglong2 hA = *(const ulonglong2*)&hk[r * 8];
                    ulonglong2 hB = *(const ulonglong2*)&hk[r * 8 + 4];
                    #pragma unroll
                    for (int g = 0; g < 4; g++) {
                        u64 wp = pack2(wreg[g*16 + r], wreg[g*16 + r]);
                        acc[g*4+0] = fma2(wp, hA.x, acc[g*4+0]);
                        acc[g*4+1] = fma2(wp, hA.y, acc[g*4+1]);
                        acc[g*4+2] = fma2(wp, hB.x, acc[g*4+2]);
                        acc[g*4+3] = fma2(wp, hB.y, acc[g*4+3]);
                    }
                }
                // butterfly over the 4 k-quarters (lane bits 0-1)
                #pragma unroll
                for (int a = 0; a < 16; a++)
                    acc[a] = add2(acc[a], __shfl_xor_sync(0xffffffffu, acc[a], 1));
                #pragma unroll
                for (int a = 0; a < 16; a++)
                    acc[a] = add2(acc[a], __shfl_xor_sync(0xffffffffu, acc[a], 2));

                // cell j, batches 2q, 2q+1 (bp = qq)
                float i0, i1, f0, f1, g0, g1, o0, o1;
                unpack2(acc[0*4 + qq], i0, i1);
                unpack2(acc[1*4 + qq], f0, f1);
                unpack2(acc[2*4 + qq], g0, g1);
                unpack2(acc[3*4 + qq], o0, o1);
                float nc0 = sigf(f0) * c0 + sigf(i0) * tanh_f(g0); c0 = nc0;
                float nc1 = sigf(f1) * c1 + sigf(i1) * tanh_f(g1); c1 = nc1;
                float h0 = sigf(o0) * tanh_f(nc0);
                float h1v = sigf(o1) * tanh_f(nc1);
                *(u64*)&hn[jj * 8 + 2 * qq] = pack2(h0, h1v);
            }
        } else {
            if (i >= 1) {
                u64 acc[16];
                if (qq == 0) {
                    #pragma unroll
                    for (int g = 0; g < 4; g++) {
                        acc[g*4+0] = wep[g]; acc[g*4+1] = wep[g];
                        acc[g*4+2] = wep[g]; acc[g*4+3] = wep[g];
                    }
                } else {
                    #pragma unroll
                    for (int a = 0; a < 16; a++) acc[a] = 0ULL;
                }
                const float* hk = hc + qq * 96;    // rows [12q, 12q+12)
                #pragma unroll
                for (int r = 0; r < 12; r++) {
                    ulonglong2 hA = *(const ulonglong2*)&hk[r * 8];
                    ulonglong2 hB = *(const ulonglong2*)&hk[r * 8 + 4];
                    #pragma unroll
                    for (int g = 0; g < 4; g++) {
                        u64 wp = pack2(wreg[g*12 + r], wreg[g*12 + r]);
                        acc[g*4+0] = fma2(wp, hA.x, acc[g*4+0]);
                        acc[g*4+1] = fma2(wp, hA.y, acc[g*4+1]);
                        acc[g*4+2] = fma2(wp, hB.x, acc[g*4+2]);
                        acc[g*4+3] = fma2(wp, hB.y, acc[g*4+3]);
                    }
                }
                // butterfly over the 8 k-splits (lane bits 0-2)
                #pragma unroll
                for (int a = 0; a < 16; a++)
                    acc[a] = add2(acc[a], __shfl_xor_sync(0xffffffffu, acc[a], 1));
                #pragma unroll
                for (int a = 0; a < 16; a++)
                    acc[a] = add2(acc[a], __shfl_xor_sync(0xffffffffu, acc[a], 2));
                #pragma unroll
                for (int a = 0; a < 16; a++)
                    acc[a] = add2(acc[a], __shfl_xor_sync(0xffffffffu, acc[a], 4));

                // cell j, batch q (bp = q>>1, half = q&1)
                int bp = qq >> 1;
                float v0, v1;
                float gi, gf, gg, go;
                unpack2(acc[0*4 + bp], v0, v1); gi = (qq & 1) ? v1 : v0;
                unpack2(acc[1*4 + bp], v0, v1); gf = (qq & 1) ? v1 : v0;
                unpack2(acc[2*4 + bp], v0, v1); gg = (qq & 1) ? v1 : v0;
                unpack2(acc[3*4 + bp], v0, v1); go = (qq & 1) ? v1 : v0;
                float nc = sigf(gf) * c0 + sigf(gi) * tanh_f(gg); c0 = nc;
                hn[(64 + jj) * 8 + qq] = sigf(go) * tanh_f(nc);
            }
        }
        __syncthreads();
    }

    // ---- qkv projection of l2_final = h2(15) + h1(15)[:32] ----
    // h1(15) in hcat buffer 0 rows 0-63; h2(15) in hcat buffer 1 rows 64-95.
    for (int oi = tid; oi < 768; oi += 512) {
        int b = oi / 96, g = oi % 96;
        float acc = attn_b[g];
        #pragma unroll 8
        for (int e = 0; e < 32; e++) {
            float vv = hcat[e * 8 + b] + hcat[768 + (64 + e) * 8 + b];
            acc = fmaf(vv, attn_w[g * 32 + e], acc);
        }
        int m = b0 + b;
        int head = (g & 31) >> 3;
        int d = g & 7;
        if (g < 32)      q_g[head * 8192 + m * 8 + d] = acc * 0.3535533905932738f;
        else if (g < 64) k_g[head * 8192 + m * 8 + d] = acc;
        else             v_g[head * 8192 + m * 8 + d] = acc;
    }
}

// =====================================================================
// Kernel 2: attention partials. grid (128 row-blocks, 2 key-halves),
//   256 thr; warp = (head, 4-row group); 512 keys per warp (16 iters),
//   k/v direct from L1/L2. Partial (sum, acc) to global (additive —
//   no max subtraction).
// =====================================================================
__global__ void __launch_bounds__(256, 2) attn_kernel()
{
    const int tid = threadIdx.x;
    const int lane = tid & 31, w = tid >> 5;
    const int rb = blockIdx.x, kh = blockIdx.y;
    const int head = w & 3;
    const int rg = w >> 2;          // 0 or 1
    const int r0 = rb * 8 + rg * 4;

    const float* qbase = q_g + head * 8192 + r0 * 8;
    float4 qa[4], qb[4];
    #pragma unroll
    for (int r = 0; r < 4; r++) {
        const float4* qp = (const float4*)(qbase + r * 8);
        qa[r] = qp[0]; qb[r] = qp[1];
    }

    const float4* kg = (const float4*)(k_g + head * 8192 + kh * 4096);
    const float4* vg = (const float4*)(v_g + head * 8192 + kh * 4096);

    float sums[4] = {0.f, 0.f, 0.f, 0.f};
    float acc[4][8];
    #pragma unroll
    for (int r = 0; r < 4; r++)
        #pragma unroll
        for (int d = 0; d < 8; d++) acc[r][d] = 0.f;

    #pragma unroll 2
    for (int mi = 0; mi < 16; mi++) {
        int m = lane + mi * 32;
        float4 ka = kg[m * 2], kb = kg[m * 2 + 1];
        float4 va = vg[m * 2], vb = vg[m * 2 + 1];
        #pragma unroll
        for (int r = 0; r < 4; r++) {
            float s = qa[r].x * ka.x;
            s = fmaf(qa[r].y, ka.y, s);
            s = fmaf(qa[r].z, ka.z, s);
            s = fmaf(qa[r].w, ka.w, s);
            s = fmaf(qb[r].x, kb.x, s);
            s = fmaf(qb[r].y, kb.y, s);
            s = fmaf(qb[r].z, kb.z, s);
            s = fmaf(qb[r].w, kb.w, s);
            float e = __expf(s);
            sums[r] += e;
            acc[r][0] = fmaf(e, va.x, acc[r][0]);
            acc[r][1] = fmaf(e, va.y, acc[r][1]);
            acc[r][2] = fmaf(e, va.z, acc[r][2]);
            acc[r][3] = fmaf(e, va.w, acc[r][3]);
            acc[r][4] = fmaf(e, vb.x, acc[r][4]);
            acc[r][5] = fmaf(e, vb.y, acc[r][5]);
            acc[r][6] = fmaf(e, vb.z, acc[r][6]);
            acc[r][7] = fmaf(e, vb.w, acc[r][7]);
        }
    }
    // butterfly reduce across the warp
    #pragma unroll
    for (int o = 16; o > 0; o >>= 1) {
        #pragma unroll
        for (int r = 0; r < 4; r++) {
            sums[r] += __shfl_xor_sync(0xffffffffu, sums[r], o);
            #pragma unroll
            for (int d = 0; d < 8; d++)
                acc[r][d] += __shfl_xor_sync(0xffffffffu, acc[r][d], o);
        }
    }
    if (lane < 4) {
        int row = r0 + lane;
        int idx = (row * 4 + head) * 2 + kh;
        float4* ap = (float4*)(accp_g + idx * 8);
        ap[0] = make_float4(acc[lane][0], acc[lane][1], acc[lane][2], acc[lane][3]);
        ap[1] = make_float4(acc[lane][4], acc[lane][5], acc[lane][6], acc[lane][7]);
        sump_g[idx] = sums[lane];
    }
}

// =====================================================================
// Kernel 3: combine partials + attn output proj + MLP head.
//   128 CTAs x 256 thr, 8 rows each.
// =====================================================================
__global__ void __launch_bounds__(256, 1) mlp_kernel(
    const float* __restrict__ ow, const float* __restrict__ ob,
    const float* __restrict__ d1w, const float* __restrict__ d1b,
    const float* __restrict__ bg1, const float* __restrict__ bb1,
    const float* __restrict__ d2w, const float* __restrict__ d2b,
    const float* __restrict__ bg2, const float* __restrict__ bb2,
    const float* __restrict__ d3w, const float* __restrict__ d3b,
    float* __restrict__ out)
{
    __shared__ float owT[1024], d1T[2048], d2T[2048], d3s[32];
    __shared__ float obs[32], d1bs[64], d2bs[32], s1v[64], sb1[64], s2v[32], sb2[32];
    __shared__ float att[8 * 32], z1[8 * 32], z2[8 * 64], z3[32 * 8];

    const int tid = threadIdx.x;
    const int r0 = blockIdx.x * 8;
    const float bnscale = rsqrtf(1.f + 1e-5f);

    // ---- stage MLP weights ----
    for (int i = tid; i < 1024; i += 256) { int o = i & 31, e = i >> 5; owT[e * 32 + o] = ow[o * 32 + e]; }
    for (int i = tid; i < 2048; i += 256) { int o = i & 63, e = i >> 6; d1T[e * 64 + o] = d1w[o * 32 + e]; }
    for (int i = tid; i < 2048; i += 256) { int o = i & 31, e = i >> 5; d2T[e * 32 + o] = d2w[o * 64 + e]; }
    if (tid < 32) { d3s[tid] = d3w[tid]; obs[tid] = ob[tid]; d2bs[tid] = d2b[tid]; s2v[tid] = bg2[tid] * bnscale; sb2[tid] = bb2[tid]; }
    if (tid < 64) { d1bs[tid] = d1b[tid]; s1v[tid] = bg1[tid] * bnscale; sb1[tid] = bb1[tid]; }

    // ---- combine attention partials: att[b][e] ----
    {
        int b = tid >> 5, e = tid & 31;
        int head = e >> 3, d = e & 7;
        int pbase = ((r0 + b) * 4 + head) * 2;
        float s = sump_g[pbase] + sump_g[pbase + 1];
        float a = accp_g[pbase * 8 + d] + accp_g[(pbase + 1) * 8 + d];
        att[b * 32 + e] = a / s;
    }
    __syncthreads();

    // ---- attention output projection: 8x32 = 256 outputs ----
    {
        int b = tid >> 5, o = tid & 31;
        float a = obs[o];
        #pragma unroll 8
        for (int e = 0; e < 32; e++) a += att[b * 32 + e] * owT[e * 32 + o];
        z1[b * 32 + o] = a;
    }
    __syncthreads();

    // ---- dense1 + bn1 + relu: 8x64 = 512 outputs ----
    for (int i = tid; i < 512; i += 256) {
        int b = i >> 6, o = i & 63;
        float a = d1bs[o];
        #pragma unroll 8
        for (int e = 0; e < 32; e++) a += z1[b * 32 + e] * d1T[e * 64 + o];
        a = a * s1v[o] + sb1[o];
        z2[b * 64 + o] = fmaxf(a, 0.f);
    }
    __syncthreads();

    // ---- dense2 + bn2 + relu: 8x32 (store transposed [o][b]) ----
    {
        int b = tid >> 5, o = tid & 31;
        float a = d2bs[o];
        #pragma unroll 8
        for (int e = 0; e < 64; e++) a += z2[b * 64 + e] * d2T[e * 32 + o];
        a = a * s2v[o] + sb2[o];
        z3[o * 8 + b] = fmaxf(a, 0.f);
    }
    __syncthreads();

    // ---- dense3 + sigmoid ----
    if (tid < 8) {
        int b = tid;
        float a = d3b[0];
        #pragma unroll 8
        for (int e = 0; e < 32; e++) a += z3[e * 8 + b] * d3s[e];
        out[r0 + b] = 1.f / (1.f + __expf(-a));
    }
}

// =====================================================================
extern "C" void kernel_launch(void* const* d_in, const int* in_sizes, int n_in,
                              void* d_out, int out_size)
{
    const float* x      = (const float*)d_in[0];
    const float* emb_w  = (const float*)d_in[1];
    const float* emb_b  = (const float*)d_in[2];
    const float* l1_wih = (const float*)d_in[3];
    const float* l1_whh = (const float*)d_in[4];
    const float* l1_bih = (const float*)d_in[5];
    const float* l1_bhh = (const float*)d_in[6];
    const float* l2_wih = (const float*)d_in[7];
    const float* l2_whh = (const float*)d_in[8];
    const float* l2_bih = (const float*)d_in[9];
    const float* l2_bhh = (const float*)d_in[10];
    const float* attn_w = (const float*)d_in[11];
    const float* attn_b = (const float*)d_in[12];
    const float* attn_ow = (const float*)d_in[13];
    const float* attn_ob = (const float*)d_in[14];
    const float* d1_w   = (const float*)d_in[15];
    const float* d1_b   = (const float*)d_in[16];
    const float* bn1_g  = (const float*)d_in[17];
    const float* bn1_b  = (const float*)d_in[18];
    const float* d2_w   = (const float*)d_in[19];
    const float* d2_b   = (const float*)d_in[20];
    const float* bn2_g  = (const float*)d_in[21];
    const float* bn2_b  = (const float*)d_in[22];
    const float* d3_w   = (const float*)d_in[23];
    const float* d3_b   = (const float*)d_in[24];
    float* out = (float*)d_out;

    const int smem1 = 6336 * 4;   // 25,344 B
    cudaFuncSetAttribute(lstm_kernel, cudaFuncAttributeMaxDynamicSharedMemorySize, smem1);

    lstm_kernel<<<128, 512, smem1>>>(x, emb_w, emb_b,
                                     l1_wih, l1_whh, l1_bih, l1_bhh,
                                     l2_wih, l2_whh, l2_bih, l2_bhh,
                                     attn_w, attn_b);
    attn_kernel<<<dim3(128, 2), 256>>>();
    mlp_kernel<<<128, 256>>>(attn_ow, attn_ob, d1_w, d1_b,
                             bn1_g, bn1_b, d2_w, d2_b,
                             bn2_g, bn2_b, d3_w, d3_b, out);
}

// round 11
// speedup vs baseline: 2.2350x; 2.2350x over previous
#include <cuda_runtime.h>
#include <math.h>

// ---------------- global scratch (no allocations allowed) ----------------
__device__ float q_g[4 * 1024 * 8];
__device__ float k_g[4 * 1024 * 8];
__device__ float v_g[4 * 1024 * 8];

typedef unsigned long long u64;

__device__ __forceinline__ float tanh_f(float x) {
    float y; asm("tanh.approx.f32 %0, %1;" : "=f"(y) : "f"(x)); return y;
}
__device__ __forceinline__ float sigf(float x) {
    return fmaf(0.5f, tanh_f(0.5f * x), 0.5f);
}
__device__ __forceinline__ u64 pack2(float a, float b) {
    u64 r; asm("mov.b64 %0, {%1,%2};" : "=l"(r) : "f"(a), "f"(b)); return r;
}
__device__ __forceinline__ void unpack2(u64 v, float& a, float& b) {
    asm("mov.b64 {%0,%1}, %2;" : "=f"(a), "=f"(b) : "l"(v));
}
__device__ __forceinline__ u64 fma2(u64 a, u64 b, u64 c) {
    u64 d; asm("fma.rn.f32x2 %0, %1, %2, %3;" : "=l"(d) : "l"(a), "l"(b), "l"(c)); return d;
}

// =====================================================================
// Kernel 1: pipelined LSTM1 + LSTM2, balanced 16-iter GEMVs.
//   (byte-identical to the round-7 best: 896 threads, A=512, B=384)
// =====================================================================
__global__ void __launch_bounds__(896, 1) lstm_kernel(
    const float* __restrict__ x,
    const float* __restrict__ emb_w, const float* __restrict__ emb_b,
    const float* __restrict__ w1, const float* __restrict__ u1,
    const float* __restrict__ b1i, const float* __restrict__ b1h,
    const float* __restrict__ w2, const float* __restrict__ u2,
    const float* __restrict__ b2i, const float* __restrict__ b2h,
    const float* __restrict__ attn_w, const float* __restrict__ attn_b)
{
    extern __shared__ __align__(16) float sm[];
    float* g1p    = sm;              // [4][8][256]  8192
    float* g2p    = g1p + 8192;     // [6][8][128]  6144
    float* pt1s   = g2p + 6144;     // [16][256]    4096
    float* pe     = pt1s + 4096;    // [16][32]      512
    float* xs     = pe + 512;       // [16][8]       128
    float* hcat   = xs + 128;       // [2][96][8]   1536
    float* embw_s = hcat + 1536;    // 32
    float* embb_s = embw_s + 32;    // 32

    const int tid = threadIdx.x;
    const int b0 = blockIdx.x * 8;

    // ---- shared prologue ----
    if (tid < 512) {
        int t = tid >> 5, e = tid & 31;
        int half = e >> 1;
        float div = __expf(-(float)(2 * half) * (9.210340371976184f / 32.0f));
        float arg = (float)t * div;
        pe[tid] = (e & 1) ? cosf(arg) : sinf(arg);
    }
    if (tid < 32) { embw_s[tid] = emb_w[tid]; embb_s[tid] = emb_b[tid]; }
    if (tid < 128) { int t = tid >> 3, b = tid & 7; xs[tid] = x[(b0 + b) * 16 + t]; }
    for (int i = tid; i < 1536; i += 896) hcat[i] = 0.f;
    __syncthreads();

    // ---- pt1s + we1 (embedding folded into LSTM1): threads < 256 ----
    if (tid < 256) {
        int gate = 2 * (tid & 127) + (tid >> 7);
        float w1r[32];
        const float4* w1p = (const float4*)(w1 + gate * 32);
        #pragma unroll
        for (int qq = 0; qq < 8; qq++) {
            float4 v = w1p[qq];
            w1r[qq*4+0]=v.x; w1r[qq*4+1]=v.y; w1r[qq*4+2]=v.z; w1r[qq*4+3]=v.w;
        }
        float we1 = 0.f, wb = b1i[gate] + b1h[gate];
        #pragma unroll
        for (int e = 0; e < 32; e++) {
            we1 = fmaf(w1r[e], embw_s[e], we1);
            wb  = fmaf(w1r[e], embb_s[e], wb);
        }
        g1p[gate] = we1;   // stash
        #pragma unroll
        for (int t = 0; t < 16; t++) {
            float s = wb;
            #pragma unroll
            for (int e = 0; e < 32; e++) s = fmaf(w1r[e], pe[t * 32 + e], s);
            pt1s[t * 256 + gate] = s;
        }
    }
    __syncthreads();

    // ---- per-thread register setup ----
    float wreg[32];
    u64 weA = 0, weB = 0, bvA = 0, bvB = 0;
    float c1r = 0.f, c2r = 0.f;
    int pA = 0, qA = 0, pB = 0, sB = 0;

    if (tid < 512) {
        pA = tid & 127; qA = tid >> 7;
        const float4* a0 = (const float4*)(u1 + (2 * pA) * 64 + qA * 16);
        const float4* a1 = (const float4*)(u1 + (2 * pA + 1) * 64 + qA * 16);
        #pragma unroll
        for (int qq = 0; qq < 4; qq++) {
            float4 v = a0[qq];
            wreg[qq*4+0]=v.x; wreg[qq*4+1]=v.y; wreg[qq*4+2]=v.z; wreg[qq*4+3]=v.w;
            float4 u = a1[qq];
            wreg[16+qq*4+0]=u.x; wreg[16+qq*4+1]=u.y; wreg[16+qq*4+2]=u.z; wreg[16+qq*4+3]=u.w;
        }
        if (qA == 0) {
            float wa = g1p[2 * pA], wbv = g1p[2 * pA + 1];
            weA = pack2(wa, wa); weB = pack2(wbv, wbv);
        }
    } else {
        int t2 = tid - 512;
        pB = t2 & 63; sB = t2 >> 6;   // sB in [0,6)
        #pragma unroll
        for (int g = 0; g < 2; g++) {
            int row = 2 * pB + g;
            const float4* p = (sB < 4)
                ? (const float4*)(w2 + row * 64 + sB * 16)
                : (const float4*)(u2 + row * 32 + (sB - 4) * 16);
            #pragma unroll
            for (int qq = 0; qq < 4; qq++) {
                float4 v = p[qq];
                wreg[g*16+qq*4+0]=v.x; wreg[g*16+qq*4+1]=v.y;
                wreg[g*16+qq*4+2]=v.z; wreg[g*16+qq*4+3]=v.w;
            }
        }
        if (sB == 0) {
            float ba = b2i[2 * pB] + b2h[2 * pB];
            float bb = b2i[2 * pB + 1] + b2h[2 * pB + 1];
            bvA = pack2(ba, ba); bvB = pack2(bb, bb);
        }
    }
    __syncthreads();   // stash in g1p consumed before main loop overwrites

    // ---- pipelined main loop: 17 iterations ----
    for (int i = 0; i < 17; ++i) {
        int cur = i & 1;
        const float* hc = hcat + cur * 768;
        float* hn = hcat + (cur ^ 1) * 768;
        if (tid < 512) {
            if (i < 16) {
                u64 a00, a01, a02, a03, a10, a11, a12, a13;
                if (qA == 0) {
                    float pt0 = pt1s[i * 256 + 2 * pA];
                    float pt1 = pt1s[i * 256 + 2 * pA + 1];
                    u64 p0 = pack2(pt0, pt0), p1 = pack2(pt1, pt1);
                    const ulonglong2* xp = (const ulonglong2*)&xs[i * 8];
                    ulonglong2 x01 = xp[0], x23 = xp[1];
                    a00 = fma2(weA, x01.x, p0); a01 = fma2(weA, x01.y, p0);
                    a02 = fma2(weA, x23.x, p0); a03 = fma2(weA, x23.y, p0);
                    a10 = fma2(weB, x01.x, p1); a11 = fma2(weB, x01.y, p1);
                    a12 = fma2(weB, x23.x, p1); a13 = fma2(weB, x23.y, p1);
                } else {
                    a00=a01=a02=a03=a10=a11=a12=a13=0ULL;
                }
                const float* hk = hc + qA * 128;
                #pragma unroll
                for (int k = 0; k < 16; k++) {
                    ulonglong2 hA = *(const ulonglong2*)&hk[k * 8];
                    ulonglong2 hB = *(const ulonglong2*)&hk[k * 8 + 4];
                    u64 w0 = pack2(wreg[k], wreg[k]);
                    a00 = fma2(w0, hA.x, a00); a01 = fma2(w0, hA.y, a01);
                    a02 = fma2(w0, hB.x, a02); a03 = fma2(w0, hB.y, a03);
                    u64 w1p = pack2(wreg[16 + k], wreg[16 + k]);
                    a10 = fma2(w1p, hA.x, a10); a11 = fma2(w1p, hA.y, a11);
                    a12 = fma2(w1p, hB.x, a12); a13 = fma2(w1p, hB.y, a13);
                }
                float f0, f1;
                float* gp0 = g1p + qA * 2048 + 2 * pA;
                unpack2(a00, f0, f1); gp0[0]    = f0; gp0[256]  = f1;
                unpack2(a01, f0, f1); gp0[512]  = f0; gp0[768]  = f1;
                unpack2(a02, f0, f1); gp0[1024] = f0; gp0[1280] = f1;
                unpack2(a03, f0, f1); gp0[1536] = f0; gp0[1792] = f1;
                float* gp1 = gp0 + 1;
                unpack2(a10, f0, f1); gp1[0]    = f0; gp1[256]  = f1;
                unpack2(a11, f0, f1); gp1[512]  = f0; gp1[768]  = f1;
                unpack2(a12, f0, f1); gp1[1024] = f0; gp1[1280] = f1;
                unpack2(a13, f0, f1); gp1[1536] = f0; gp1[1792] = f1;

                asm volatile("bar.sync 1, 512;" ::: "memory");

                // cell update: one cell per thread, sum 4 quarters
                int b = tid >> 6, j = tid & 63;
                const float* gp = g1p + b * 256 + j;
                float gi = gp[0]       + gp[2048]      + gp[4096]      + gp[6144];
                float gf = gp[64]      + gp[2048+64]   + gp[4096+64]   + gp[6144+64];
                float gg = gp[128]     + gp[2048+128]  + gp[4096+128]  + gp[6144+128];
                float go = gp[192]     + gp[2048+192]  + gp[4096+192]  + gp[6144+192];
                float nc = sigf(gf) * c1r + sigf(gi) * tanh_f(gg);
                c1r = nc;
                hn[j * 8 + b] = sigf(go) * tanh_f(nc);
            }
        } else {
            if (i >= 1) {
                int t2 = tid - 512;
                u64 a00, a01, a02, a03, a10, a11, a12, a13;
                if (sB == 0) { a00=a01=a02=a03=bvA; a10=a11=a12=a13=bvB; }
                else { a00=a01=a02=a03=a10=a11=a12=a13=0ULL; }
                const float* hk = hc + sB * 128;   // 16 rows per split
                #pragma unroll
                for (int c = 0; c < 16; c++) {
                    ulonglong2 hA = *(const ulonglong2*)&hk[c * 8];
                    ulonglong2 hB = *(const ulonglong2*)&hk[c * 8 + 4];
                    u64 w0 = pack2(wreg[c], wreg[c]);
                    a00 = fma2(w0, hA.x, a00); a01 = fma2(w0, hA.y, a01);
                    a02 = fma2(w0, hB.x, a02); a03 = fma2(w0, hB.y, a03);
                    u64 w1p = pack2(wreg[16 + c], wreg[16 + c]);
                    a10 = fma2(w1p, hA.x, a10); a11 = fma2(w1p, hA.y, a11);
                    a12 = fma2(w1p, hB.x, a12); a13 = fma2(w1p, hB.y, a13);
                }
                float f0, f1;
                float* gp0 = g2p + sB * 1024 + 2 * pB;
                unpack2(a00, f0, f1); gp0[0]   = f0; gp0[128] = f1;
                unpack2(a01, f0, f1); gp0[256] = f0; gp0[384] = f1;
                unpack2(a02, f0, f1); gp0[512] = f0; gp0[640] = f1;
                unpack2(a03, f0, f1); gp0[768] = f0; gp0[896] = f1;
                float* gp1 = gp0 + 1;
                unpack2(a10, f0, f1); gp1[0]   = f0; gp1[128] = f1;
                unpack2(a11, f0, f1); gp1[256] = f0; gp1[384] = f1;
                unpack2(a12, f0, f1); gp1[512] = f0; gp1[640] = f1;
                unpack2(a13, f0, f1); gp1[768] = f0; gp1[896] = f1;

                asm volatile("bar.sync 2, 384;" ::: "memory");

                // cell update: one cell per thread (first 256), sum 6 splits
                if (t2 < 256) {
                    int b = t2 >> 5, j = t2 & 31;
                    const float* gp = g2p + b * 128 + j;
                    float gi = 0.f, gf = 0.f, gg = 0.f, go = 0.f;
                    #pragma unroll
                    for (int s = 0; s < 6; s++) {
                        gi += gp[s * 1024];
                        gf += gp[s * 1024 + 32];
                        gg += gp[s * 1024 + 64];
                        go += gp[s * 1024 + 96];
                    }
                    float nc = sigf(gf) * c2r + sigf(gi) * tanh_f(gg);
                    c2r = nc;
                    hn[(64 + j) * 8 + b] = sigf(go) * tanh_f(nc);
                }
            }
        }
        __syncthreads();
    }

    // ---- qkv projection of l2_final = h2(15) + h1(15)[:32] ----
    if (tid < 768) {
        int b = tid / 96, g = tid % 96;
        float acc = attn_b[g];
        #pragma unroll 8
        for (int e = 0; e < 32; e++) {
            float vv = hcat[e * 8 + b] + hcat[768 + (64 + e) * 8 + b];
            acc = fmaf(vv, attn_w[g * 32 + e], acc);
        }
        int m = b0 + b;
        int head = (g & 31) >> 3;
        int d = g & 7;
        if (g < 32)      q_g[head * 8192 + m * 8 + d] = acc * 0.3535533905932738f;
        else if (g < 64) k_g[head * 8192 + m * 8 + d] = acc;
        else             v_g[head * 8192 + m * 8 + d] = acc;
    }
}

// =====================================================================
// Kernel 2: fused attention + MLP head, 128 CTAs x 512 thr, 8 rows each.
//   warp w: head = w&3, rowgroup rg = (w>>2)&1 (4 rows), keyhalf kh = w>>3.
//   Each warp sweeps 512 keys (16 iters) direct from L1/L2; partials
//   (sum, acc[8]) combine through a small smem buffer inside the block;
//   then the MLP head runs on the same threads. One launch, no global
//   partial roundtrip.
// =====================================================================
__global__ void __launch_bounds__(512, 1) attn_mlp_kernel(
    const float* __restrict__ ow, const float* __restrict__ ob,
    const float* __restrict__ d1w, const float* __restrict__ d1b,
    const float* __restrict__ bg1, const float* __restrict__ bb1,
    const float* __restrict__ d2w, const float* __restrict__ d2b,
    const float* __restrict__ bg2, const float* __restrict__ bb2,
    const float* __restrict__ d3w, const float* __restrict__ d3b,
    float* __restrict__ out)
{
    __shared__ float owT[1024], d1T[2048], d2T[2048], d3s[32];
    __shared__ float obs[32], d1bs[64], d2bs[32], s1v[64], sb1[64], s2v[32], sb2[32];
    __shared__ float part[2][8][4][12];   // [kh][row][head][8 acc + sum], padded
    __shared__ float att[8 * 32], z1[8 * 32], z2[8 * 64], z3[32 * 8];

    const int tid = threadIdx.x;
    const int lane = tid & 31, w = tid >> 5;
    const int r0 = blockIdx.x * 8;
    const float bnscale = rsqrtf(1.f + 1e-5f);

    // ---- stage MLP weights (512-thread strides) ----
    for (int i = tid; i < 1024; i += 512) { int o = i & 31, e = i >> 5; owT[e * 32 + o] = ow[o * 32 + e]; }
    for (int i = tid; i < 2048; i += 512) { int o = i & 63, e = i >> 6; d1T[e * 64 + o] = d1w[o * 32 + e]; }
    for (int i = tid; i < 2048; i += 512) { int o = i & 31, e = i >> 5; d2T[e * 32 + o] = d2w[o * 64 + e]; }
    if (tid < 32) { d3s[tid] = d3w[tid]; obs[tid] = ob[tid]; d2bs[tid] = d2b[tid]; s2v[tid] = bg2[tid] * bnscale; sb2[tid] = bb2[tid]; }
    if (tid < 64) { d1bs[tid] = d1b[tid]; s1v[tid] = bg1[tid] * bnscale; sb1[tid] = bb1[tid]; }

    // ---- attention partials: warp = (head, 4-row group, key-half) ----
    {
        const int head = w & 3;
        const int rg = (w >> 2) & 1;
        const int kh = w >> 3;
        const float* qbase = q_g + head * 8192 + (r0 + rg * 4) * 8;
        float4 qa[4], qb[4];
        #pragma unroll
        for (int r = 0; r < 4; r++) {
            const float4* qp = (const float4*)(qbase + r * 8);
            qa[r] = qp[0]; qb[r] = qp[1];
        }

        const float4* kg = (const float4*)(k_g + head * 8192 + kh * 4096);
        const float4* vg = (const float4*)(v_g + head * 8192 + kh * 4096);

        float sums[4] = {0.f, 0.f, 0.f, 0.f};
        float acc[4][8];
        #pragma unroll
        for (int r = 0; r < 4; r++)
            #pragma unroll
            for (int d = 0; d < 8; d++) acc[r][d] = 0.f;

        #pragma unroll 2
        for (int mi = 0; mi < 16; mi++) {
            int m = lane + mi * 32;
            float4 ka = kg[m * 2], kb = kg[m * 2 + 1];
            float4 va = vg[m * 2], vb = vg[m * 2 + 1];
            #pragma unroll
            for (int r = 0; r < 4; r++) {
                float s = qa[r].x * ka.x;
                s = fmaf(qa[r].y, ka.y, s);
                s = fmaf(qa[r].z, ka.z, s);
                s = fmaf(qa[r].w, ka.w, s);
                s = fmaf(qb[r].x, kb.x, s);
                s = fmaf(qb[r].y, kb.y, s);
                s = fmaf(qb[r].z, kb.z, s);
                s = fmaf(qb[r].w, kb.w, s);
                float e = __expf(s);
                sums[r] += e;
                acc[r][0] = fmaf(e, va.x, acc[r][0]);
                acc[r][1] = fmaf(e, va.y, acc[r][1]);
                acc[r][2] = fmaf(e, va.z, acc[r][2]);
                acc[r][3] = fmaf(e, va.w, acc[r][3]);
                acc[r][4] = fmaf(e, vb.x, acc[r][4]);
                acc[r][5] = fmaf(e, vb.y, acc[r][5]);
                acc[r][6] = fmaf(e, vb.z, acc[r][6]);
                acc[r][7] = fmaf(e, vb.w, acc[r][7]);
            }
        }
        // butterfly reduce across the warp
        #pragma unroll
        for (int o = 16; o > 0; o >>= 1) {
            #pragma unroll
            for (int r = 0; r < 4; r++) {
                sums[r] += __shfl_xor_sync(0xffffffffu, sums[r], o);
                #pragma unroll
                for (int d = 0; d < 8; d++)
                    acc[r][d] += __shfl_xor_sync(0xffffffffu, acc[r][d], o);
            }
        }
        if (lane < 4) {
            int row = rg * 4 + lane;
            float* pp = &part[kh][row][head][0];
            #pragma unroll
            for (int d = 0; d < 8; d++) pp[d] = acc[lane][d];
            pp[8] = sums[lane];
        }
    }
    __syncthreads();

    // ---- combine halves: att[b][e] ----
    if (tid < 256) {
        int b = tid >> 5, e = tid & 31;
        int head = e >> 3, d = e & 7;
        float a = part[0][b][head][d] + part[1][b][head][d];
        float s = part[0][b][head][8] + part[1][b][head][8];
        att[b * 32 + e] = a / s;
    }
    __syncthreads();

    // ---- attention output projection: 8x32 = 256 outputs ----
    if (tid < 256) {
        int b = tid >> 5, o = tid & 31;
        float a = obs[o];
        #pragma unroll 8
        for (int e = 0; e < 32; e++) a += att[b * 32 + e] * owT[e * 32 + o];
        z1[b * 32 + o] = a;
    }
    __syncthreads();

    // ---- dense1 + bn1 + relu: 8x64 = 512 outputs ----
    {
        int b = tid >> 6, o = tid & 63;
        float a = d1bs[o];
        #pragma unroll 8
        for (int e = 0; e < 32; e++) a += z1[b * 32 + e] * d1T[e * 64 + o];
        a = a * s1v[o] + sb1[o];
        z2[b * 64 + o] = fmaxf(a, 0.f);
    }
    __syncthreads();

    // ---- dense2 + bn2 + relu: 8x32 (store transposed [o][b]) ----
    if (tid < 256) {
        int b = tid >> 5, o = tid & 31;
        float a = d2bs[o];
        #pragma unroll 8
        for (int e = 0; e < 64; e++) a += z2[b * 64 + e] * d2T[e * 32 + o];
        a = a * s2v[o] + sb2[o];
        z3[o * 8 + b] = fmaxf(a, 0.f);
    }
    __syncthreads();

    // ---- dense3 + sigmoid ----
    if (tid < 8) {
        int b = tid;
        float a = d3b[0];
        #pragma unroll 8
        for (int e = 0; e < 32; e++) a += z3[e * 8 + b] * d3s[e];
        out[r0 + b] = 1.f / (1.f + __expf(-a));
    }
}

// =====================================================================
extern "C" void kernel_launch(void* const* d_in, const int* in_sizes, int n_in,
                              void* d_out, int out_size)
{
    const float* x      = (const float*)d_in[0];
    const float* emb_w  = (const float*)d_in[1];
    const float* emb_b  = (const float*)d_in[2];
    const float* l1_wih = (const float*)d_in[3];
    const float* l1_whh = (const float*)d_in[4];
    const float* l1_bih = (const float*)d_in[5];
    const float* l1_bhh = (const float*)d_in[6];
    const float* l2_wih = (const float*)d_in[7];
    const float* l2_whh = (const float*)d_in[8];
    const float* l2_bih = (const float*)d_in[9];
    const float* l2_bhh = (const float*)d_in[10];
    const float* attn_w = (const float*)d_in[11];
    const float* attn_b = (const float*)d_in[12];
    const float* attn_ow = (const float*)d_in[13];
    const float* attn_ob = (const float*)d_in[14];
    const float* d1_w   = (const float*)d_in[15];
    const float* d1_b   = (const float*)d_in[16];
    const float* bn1_g  = (const float*)d_in[17];
    const float* bn1_b  = (const float*)d_in[18];
    const float* d2_w   = (const float*)d_in[19];
    const float* d2_b   = (const float*)d_in[20];
    const float* bn2_g  = (const float*)d_in[21];
    const float* bn2_b  = (const float*)d_in[22];
    const float* d3_w   = (const float*)d_in[23];
    const float* d3_b   = (const float*)d_in[24];
    float* out = (float*)d_out;

    const int smem1 = 20672 * 4;   // 82,688 B
    cudaFuncSetAttribute(lstm_kernel, cudaFuncAttributeMaxDynamicSharedMemorySize, smem1);

    lstm_kernel<<<128, 896, smem1>>>(x, emb_w, emb_b,
                                     l1_wih, l1_whh, l1_bih, l1_bhh,
                                     l2_wih, l2_whh, l2_bih, l2_bhh,
                                     attn_w, attn_b);
    attn_mlp_kernel<<<128, 512>>>(attn_ow, attn_ob, d1_w, d1_b,
                                  bn1_g, bn1_b, d2_w, d2_b,
                                  bn2_g, bn2_b, d3_w, d3_b, out);
}